// round 1
// baseline (speedup 1.0000x reference)
#include <cuda_runtime.h>
#include <math.h>

// ---------------- problem constants ----------------
#define B_SZ 2
#define T_SZ 1024
#define D_SZ 1024
#define H_SZ 16
#define DH_SZ 64
#define FF_SZ 4096
#define L_SZ 2
#define V_SZ 32000
#define M_BLK 32
#define BS_SZ 32
#define TOPK 8
#define KEEP 128          // int(513 * 0.25)
#define EPSF 1e-6f
#define PI_D 3.14159265358979323846

// ---------------- scratch (device globals; no allocation allowed) ----------------
__device__ float d_x [B_SZ*T_SZ*D_SZ];
__device__ float d_h [B_SZ*T_SZ*D_SZ];
__device__ float d_q [B_SZ*T_SZ*D_SZ];
__device__ float d_k [B_SZ*T_SZ*D_SZ];
__device__ float d_v [B_SZ*T_SZ*D_SZ];
__device__ float d_o [B_SZ*T_SZ*D_SZ];
__device__ float d_sc[(size_t)B_SZ*H_SZ*T_SZ*T_SZ];   // 128 MB
__device__ float d_f1[B_SZ*T_SZ*FF_SZ];
__device__ float d_f3[B_SZ*T_SZ*FF_SZ];
__device__ float d_G [T_SZ*T_SZ];
__device__ float d_gk[T_SZ];
__device__ float d_rho[B_SZ*T_SZ];
__device__ int   d_sel[B_SZ*M_BLK];

// ---------------- generic tiled SGEMM: C[M,N] (+)= A[M,K] @ B[K,N] ----------------
// BM=128, BN=64, BK=16; 256 threads; 8x4 per-thread tile.
// Requires: M%128==0, N%64==0, K%16==0, lda/ldb/ldc %4==0 (true for all call sites).
// Two-level batch: z -> (zb = z/Hdim, zh = z%Hdim), offsets zb*s?b + zh*s?h.
#define BM 128
#define BN 64
#define BK 16

__global__ __launch_bounds__(256) void sgemm_kernel(
    const float* __restrict__ Ag, const float* __restrict__ Bg, float* __restrict__ Cg,
    int M, int N, int K, int lda, int ldb, int ldc,
    long sAb, long sBb, long sCb, long sAh, long sBh, long sCh, int Hdim, int beta)
{
    __shared__ float As[BK][BM + 4];   // padded stride 132 (16B aligned, reduces STS conflicts)
    __shared__ float Bs[BK][BN];

    int z  = blockIdx.z;
    int zb = z / Hdim, zh = z % Hdim;
    const float* A = Ag + zb * sAb + zh * sAh;
    const float* Bp = Bg + zb * sBb + zh * sBh;
    float* C = Cg + zb * sCb + zh * sCh;

    int tid = threadIdx.x;
    int tx = tid & 15, ty = tid >> 4;
    int row0 = blockIdx.y * BM;
    int col0 = blockIdx.x * BN;

    float acc[8][4];
#pragma unroll
    for (int i = 0; i < 8; i++)
#pragma unroll
        for (int j = 0; j < 4; j++) acc[i][j] = 0.f;

    int ar0 = tid >> 2;       // 0..63 (two rows per thread: +0, +64)
    int ac4 = tid & 3;        // which float4 along K
    int br  = tid >> 4;       // 0..15
    int bc4 = tid & 15;       // float4 along N

    for (int kt = 0; kt < K; kt += BK) {
#pragma unroll
        for (int i = 0; i < 2; i++) {
            int r = ar0 + i * 64;
            float4 va = *reinterpret_cast<const float4*>(
                A + (size_t)(row0 + r) * lda + kt + ac4 * 4);
            As[ac4 * 4 + 0][r] = va.x;
            As[ac4 * 4 + 1][r] = va.y;
            As[ac4 * 4 + 2][r] = va.z;
            As[ac4 * 4 + 3][r] = va.w;
        }
        {
            float4 vb = *reinterpret_cast<const float4*>(
                Bp + (size_t)(kt + br) * ldb + col0 + bc4 * 4);
            *reinterpret_cast<float4*>(&Bs[br][bc4 * 4]) = vb;
        }
        __syncthreads();

#pragma unroll
        for (int kk = 0; kk < BK; kk++) {
            float4 a0 = *reinterpret_cast<const float4*>(&As[kk][ty * 8]);
            float4 a1 = *reinterpret_cast<const float4*>(&As[kk][ty * 8 + 4]);
            float4 b0 = *reinterpret_cast<const float4*>(&Bs[kk][tx * 4]);
            float ra[8] = {a0.x, a0.y, a0.z, a0.w, a1.x, a1.y, a1.z, a1.w};
            float rb[4] = {b0.x, b0.y, b0.z, b0.w};
#pragma unroll
            for (int i = 0; i < 8; i++)
#pragma unroll
                for (int j = 0; j < 4; j++)
                    acc[i][j] = fmaf(ra[i], rb[j], acc[i][j]);
        }
        __syncthreads();
    }

#pragma unroll
    for (int i = 0; i < 8; i++) {
        size_t cidx = (size_t)(row0 + ty * 8 + i) * ldc + col0 + tx * 4;
        float4 outv;
        outv.x = acc[i][0]; outv.y = acc[i][1]; outv.z = acc[i][2]; outv.w = acc[i][3];
        if (beta) {
            float4 prev = *reinterpret_cast<const float4*>(C + cidx);
            outv.x += prev.x; outv.y += prev.y; outv.z += prev.z; outv.w += prev.w;
        }
        *reinterpret_cast<float4*>(C + cidx) = outv;
    }
}

// ---------------- embedding gather ----------------
__global__ void embed_kernel(const int* __restrict__ ids, const float* __restrict__ emb,
                             float* __restrict__ x)
{
    int idx = blockIdx.x * blockDim.x + threadIdx.x;   // B*T*D
    int d = idx & (D_SZ - 1);
    int bt = idx >> 10;
    x[idx] = emb[(size_t)ids[bt] * D_SZ + d];
}

// ---------------- Dirichlet low-pass kernel table ----------------
__global__ void dirichlet_kernel(float* __restrict__ g)
{
    int d = blockIdx.x * blockDim.x + threadIdx.x;     // 0..1023
    if (d >= T_SZ) return;
    double s = 0.0;
    for (int k = 1; k < KEEP; k++)
        s += cos(2.0 * PI_D * (double)k * (double)d / (double)T_SZ);
    g[d] = (float)((1.0 + 2.0 * s) / (double)T_SZ);
}

__global__ void buildG_kernel(const float* __restrict__ g, float* __restrict__ G)
{
    int i = blockIdx.x * blockDim.x + threadIdx.x;     // T*T
    int t = i >> 10, s = i & (T_SZ - 1);
    G[i] = g[(t - s) & (T_SZ - 1)];
}

// ---------------- rho = sum(hlp^2)/ (sum(x^2)+eps) per token ----------------
__global__ __launch_bounds__(256) void rho_kernel(const float* __restrict__ hlp,
                                                  const float* __restrict__ x,
                                                  float* __restrict__ rho)
{
    size_t row = (size_t)blockIdx.x * D_SZ;
    int tid = threadIdx.x;
    float s1 = 0.f, s2 = 0.f;
#pragma unroll
    for (int i = 0; i < 4; i++) {
        float a = hlp[row + tid + i * 256];
        float b = x  [row + tid + i * 256];
        s1 += a * a; s2 += b * b;
    }
    for (int o = 16; o > 0; o >>= 1) {
        s1 += __shfl_xor_sync(0xffffffffu, s1, o);
        s2 += __shfl_xor_sync(0xffffffffu, s2, o);
    }
    __shared__ float r1[8], r2[8];
    if ((tid & 31) == 0) { r1[tid >> 5] = s1; r2[tid >> 5] = s2; }
    __syncthreads();
    if (tid == 0) {
        float t1 = 0.f, t2 = 0.f;
        for (int i = 0; i < 8; i++) { t1 += r1[i]; t2 += r2[i]; }
        rho[blockIdx.x] = t1 / (t2 + EPSF);
    }
}

// ---------------- block quality + top-8 selection ----------------
__global__ void select_blocks(const float* __restrict__ rho, int* __restrict__ sel)
{
    __shared__ float bq[B_SZ][M_BLK];
    int tid = threadIdx.x;   // 64 threads
    if (tid < B_SZ * M_BLK) {
        int b = tid >> 5, m = tid & 31;
        float s = 0.f;
        for (int i = 0; i < BS_SZ; i++) s += rho[b * T_SZ + m * BS_SZ + i];
        bq[b][m] = s * (1.f / BS_SZ);
        sel[tid] = 0;
    }
    __syncthreads();
    if (tid < B_SZ) {
        int b = tid;
        bool picked[M_BLK];
        for (int m = 0; m < M_BLK; m++) picked[m] = false;
        for (int it = 0; it < TOPK; it++) {
            int best = -1; float bv = -3.4e38f;
            for (int m = 0; m < M_BLK; m++)
                if (!picked[m] && bq[b][m] > bv) { bv = bq[b][m]; best = m; }
            picked[best] = true;
            sel[b * M_BLK + best] = 1;
        }
    }
}

// ---------------- RMSNorm ----------------
__global__ __launch_bounds__(256) void rmsnorm_kernel(const float* __restrict__ x,
                                                      const float* __restrict__ w,
                                                      float* __restrict__ y)
{
    size_t row = (size_t)blockIdx.x * D_SZ;
    int tid = threadIdx.x;
    float v[4]; float s = 0.f;
#pragma unroll
    for (int i = 0; i < 4; i++) { v[i] = x[row + tid + i * 256]; s += v[i] * v[i]; }
    for (int o = 16; o > 0; o >>= 1) s += __shfl_xor_sync(0xffffffffu, s, o);
    __shared__ float red[8];
    if ((tid & 31) == 0) red[tid >> 5] = s;
    __syncthreads();
    float tot = 0.f;
    for (int i = 0; i < 8; i++) tot += red[i];
    float r = rsqrtf(tot * (1.f / D_SZ) + EPSF);
#pragma unroll
    for (int i = 0; i < 4; i++)
        y[row + tid + i * 256] = v[i] * r * w[tid + i * 256];
}

// ---------------- RoPE (in-place, q and k) ----------------
__global__ void rope_kernel(float* __restrict__ q, float* __restrict__ k)
{
    int idx = blockIdx.x * blockDim.x + threadIdx.x;   // B*T*H*32
    int j = idx & 31;
    int h = (idx >> 5) & (H_SZ - 1);
    int t = (idx >> 9) & (T_SZ - 1);
    int b = idx >> 19;
    float inv = (float)(1.0 / pow(10000.0, (double)(2 * j) / (double)DH_SZ));
    float fr = (float)t * inv;
    float c = cosf(fr), s = sinf(fr);
    size_t base = ((size_t)(b * T_SZ + t)) * D_SZ + h * DH_SZ + j;
    float q0 = q[base], q1 = q[base + 32];
    q[base]      = q0 * c - q1 * s;
    q[base + 32] = q1 * c + q0 * s;
    float k0 = k[base], k1 = k[base + 32];
    k[base]      = k0 * c - k1 * s;
    k[base + 32] = k1 * c + k0 * s;
}

// ---------------- masked attention scores: 64x64 tiles of Q K^T ----------------
__global__ __launch_bounds__(256) void attn_scores_kernel(
    const float* __restrict__ q, const float* __restrict__ k,
    const int* __restrict__ sel, float* __restrict__ scores)
{
    __shared__ float qs[64][65];
    __shared__ float ks[64][65];
    int bh = blockIdx.z;
    int b = bh / H_SZ, h = bh % H_SZ;
    int tq0 = blockIdx.y * 64, ts0 = blockIdx.x * 64;
    int tid = threadIdx.x;

#pragma unroll
    for (int i = 0; i < 16; i++) {
        int idx = tid + i * 256;
        int r = idx >> 6, c = idx & 63;
        qs[r][c] = q[(size_t)(b * T_SZ + tq0 + r) * D_SZ + h * DH_SZ + c];
        ks[r][c] = k[(size_t)(b * T_SZ + ts0 + r) * D_SZ + h * DH_SZ + c];
    }
    __syncthreads();

    int tx = tid & 15, ty = tid >> 4;
    float acc[4][4];
#pragma unroll
    for (int i = 0; i < 4; i++)
#pragma unroll
        for (int j = 0; j < 4; j++) acc[i][j] = 0.f;

    for (int kk = 0; kk < DH_SZ; kk++) {
        float a[4], bb[4];
#pragma unroll
        for (int i = 0; i < 4; i++) a[i] = qs[ty * 4 + i][kk];
#pragma unroll
        for (int j = 0; j < 4; j++) bb[j] = ks[tx * 4 + j][kk];
#pragma unroll
        for (int i = 0; i < 4; i++)
#pragma unroll
            for (int j = 0; j < 4; j++)
                acc[i][j] = fmaf(a[i], bb[j], acc[i][j]);
    }

    const float scale = 0.125f;   // 1/sqrt(64)
#pragma unroll
    for (int i = 0; i < 4; i++) {
        int tq = tq0 + ty * 4 + i;
#pragma unroll
        for (int j = 0; j < 4; j++) {
            int ts = ts0 + tx * 4 + j;
            bool allowed = (ts <= tq) &&
                           (sel[b * M_BLK + (ts >> 5)] || ((ts >> 5) == (tq >> 5)));
            scores[((size_t)bh * T_SZ + tq) * T_SZ + ts] =
                acc[i][j] * scale + (allowed ? 0.f : -1e9f);
        }
    }
}

// ---------------- row softmax over T ----------------
__global__ __launch_bounds__(256) void softmax_kernel(float* __restrict__ s)
{
    size_t row = (size_t)blockIdx.x * T_SZ;
    int tid = threadIdx.x;
    float v[4];
    float mx = -3.4e38f;
#pragma unroll
    for (int i = 0; i < 4; i++) { v[i] = s[row + tid + i * 256]; mx = fmaxf(mx, v[i]); }
    for (int o = 16; o > 0; o >>= 1) mx = fmaxf(mx, __shfl_xor_sync(0xffffffffu, mx, o));
    __shared__ float red[8];
    if ((tid & 31) == 0) red[tid >> 5] = mx;
    __syncthreads();
    float m = red[0];
    for (int i = 1; i < 8; i++) m = fmaxf(m, red[i]);
    __syncthreads();
    float sum = 0.f;
#pragma unroll
    for (int i = 0; i < 4; i++) { v[i] = expf(v[i] - m); sum += v[i]; }
    for (int o = 16; o > 0; o >>= 1) sum += __shfl_xor_sync(0xffffffffu, sum, o);
    if ((tid & 31) == 0) red[tid >> 5] = sum;
    __syncthreads();
    float tot = 0.f;
    for (int i = 0; i < 8; i++) tot += red[i];
    float inv = 1.f / tot;
#pragma unroll
    for (int i = 0; i < 4; i++) s[row + tid + i * 256] = v[i] * inv;
}

// ---------------- SiLU gate: f1 = silu(f1) * f3 ----------------
__global__ void silu_mul_kernel(float* __restrict__ f1, const float* __restrict__ f3)
{
    int idx = blockIdx.x * blockDim.x + threadIdx.x;
    float a = f1[idx];
    f1[idx] = a / (1.f + expf(-a)) * f3[idx];
}

// ---------------- host-side launcher ----------------
static void gemm(const float* A, const float* Bp, float* C,
                 int M, int N, int K, int lda, int ldb, int ldc,
                 long sAb, long sBb, long sCb, long sAh, long sBh, long sCh,
                 int Hdim, int nbatch, int beta)
{
    dim3 grid(N / BN, M / BM, nbatch);
    sgemm_kernel<<<grid, 256>>>(A, Bp, C, M, N, K, lda, ldb, ldc,
                                sAb, sBb, sCb, sAh, sBh, sCh, Hdim, beta);
}

extern "C" void kernel_launch(void* const* d_in, const int* in_sizes, int n_in,
                              void* d_out, int out_size)
{
    const int*   ids        = (const int*)  d_in[0];
    const float* emb        = (const float*)d_in[1];
    const float* wq         = (const float*)d_in[2];
    const float* wk         = (const float*)d_in[3];
    const float* wv         = (const float*)d_in[4];
    const float* wo         = (const float*)d_in[5];
    const float* w1         = (const float*)d_in[6];
    const float* w2         = (const float*)d_in[7];
    const float* w3         = (const float*)d_in[8];
    const float* attn_norm  = (const float*)d_in[9];
    const float* ffn_norm   = (const float*)d_in[10];
    const float* final_norm = (const float*)d_in[11];
    const float* lm_head    = (const float*)d_in[12];
    float* out = (float*)d_out;

    float *x, *h, *q, *k, *v, *o, *sc, *f1, *f3, *G, *gk, *rho;
    int* sel;
    cudaGetSymbolAddress((void**)&x,   d_x);
    cudaGetSymbolAddress((void**)&h,   d_h);
    cudaGetSymbolAddress((void**)&q,   d_q);
    cudaGetSymbolAddress((void**)&k,   d_k);
    cudaGetSymbolAddress((void**)&v,   d_v);
    cudaGetSymbolAddress((void**)&o,   d_o);
    cudaGetSymbolAddress((void**)&sc,  d_sc);
    cudaGetSymbolAddress((void**)&f1,  d_f1);
    cudaGetSymbolAddress((void**)&f3,  d_f3);
    cudaGetSymbolAddress((void**)&G,   d_G);
    cudaGetSymbolAddress((void**)&gk,  d_gk);
    cudaGetSymbolAddress((void**)&rho, d_rho);
    cudaGetSymbolAddress((void**)&sel, d_sel);

    const int BT = B_SZ * T_SZ;            // 2048
    const long DD = (long)D_SZ * D_SZ;

    // 1) embedding
    embed_kernel<<<(B_SZ * T_SZ * D_SZ) / 256, 256>>>(ids, emb, x);

    // 2) low-pass quality score -> block selection
    dirichlet_kernel<<<T_SZ / 256, 256>>>(gk);
    buildG_kernel<<<(T_SZ * T_SZ) / 256, 256>>>(gk, G);
    // hlp (into h): per-batch  h[b] = G @ x[b]
    gemm(G, x, h, T_SZ, D_SZ, T_SZ, T_SZ, D_SZ, D_SZ,
         0, (long)T_SZ * D_SZ, (long)T_SZ * D_SZ, 0, 0, 0, 1, B_SZ, 0);
    rho_kernel<<<BT, 256>>>(h, x, rho);
    select_blocks<<<1, 64>>>(rho, sel);

    // 3) transformer layers
    for (int l = 0; l < L_SZ; l++) {
        rmsnorm_kernel<<<BT, 256>>>(x, attn_norm + (size_t)l * D_SZ, h);

        gemm(h, wq + l * DD, q, BT, D_SZ, D_SZ, D_SZ, D_SZ, D_SZ,
             0, 0, 0, 0, 0, 0, 1, 1, 0);
        gemm(h, wk + l * DD, k, BT, D_SZ, D_SZ, D_SZ, D_SZ, D_SZ,
             0, 0, 0, 0, 0, 0, 1, 1, 0);
        gemm(h, wv + l * DD, v, BT, D_SZ, D_SZ, D_SZ, D_SZ, D_SZ,
             0, 0, 0, 0, 0, 0, 1, 1, 0);

        rope_kernel<<<(B_SZ * T_SZ * H_SZ * 32) / 256, 256>>>(q, k);

        attn_scores_kernel<<<dim3(T_SZ / 64, T_SZ / 64, B_SZ * H_SZ), 256>>>(q, k, sel, sc);
        softmax_kernel<<<B_SZ * H_SZ * T_SZ, 256>>>(sc);

        // o[b,:,h*64:(h+1)*64] = attn[b,h] @ v[b,:,h*64:(h+1)*64]
        gemm(sc, v, o, T_SZ, DH_SZ, T_SZ, T_SZ, D_SZ, D_SZ,
             (long)H_SZ * T_SZ * T_SZ, (long)T_SZ * D_SZ, (long)T_SZ * D_SZ,
             (long)T_SZ * T_SZ, DH_SZ, DH_SZ, H_SZ, B_SZ * H_SZ, 0);

        // x += o @ wo[l]
        gemm(o, wo + l * DD, x, BT, D_SZ, D_SZ, D_SZ, D_SZ, D_SZ,
             0, 0, 0, 0, 0, 0, 1, 1, 1);

        // FFN
        rmsnorm_kernel<<<BT, 256>>>(x, ffn_norm + (size_t)l * D_SZ, h);
        gemm(h, w1 + (size_t)l * D_SZ * FF_SZ, f1, BT, FF_SZ, D_SZ, D_SZ, FF_SZ, FF_SZ,
             0, 0, 0, 0, 0, 0, 1, 1, 0);
        gemm(h, w3 + (size_t)l * D_SZ * FF_SZ, f3, BT, FF_SZ, D_SZ, D_SZ, FF_SZ, FF_SZ,
             0, 0, 0, 0, 0, 0, 1, 1, 0);
        silu_mul_kernel<<<(BT * FF_SZ) / 256, 256>>>(f1, f3);
        gemm(f1, w2 + (size_t)l * FF_SZ * D_SZ, x, BT, D_SZ, FF_SZ, FF_SZ, D_SZ, D_SZ,
             0, 0, 0, 0, 0, 0, 1, 1, 1);
    }

    // 4) final norm + lm_head
    rmsnorm_kernel<<<BT, 256>>>(x, final_norm, h);
    gemm(h, lm_head, out, BT, V_SZ, D_SZ, D_SZ, V_SZ, V_SZ,
         0, 0, 0, 0, 0, 0, 1, 1, 0);
}